// round 17
// baseline (speedup 1.0000x reference)
#include <cuda_runtime.h>
#include <math.h>

// S4D real SSM, v11: v10's 3-kernel split with thinned hot loops.
//   passA: Taylor exp for per-state decay (no MUFU in the common path),
//          packed {x,x} ull smem tile -> mainloop = LDS.64 + 4 FFMA2.
//   scan : unchanged.
//   passC: packed tile + tree-form dot (shorter serial chain), butterfly
//          epilogue unchanged.

#define LEN   4096
#define CH    512
#define S     64
#define NC    64            // chunks over L
#define LC    64            // chunk length
#define CS    (CH*S)        // 32768 states
#define DTF   (1.0f/4096.0f)

#define SPL   8             // states per lane
#define NPK   4             // packed f32x2 pairs per lane
#define CPW   4             // channels per warp
#define CPB   32            // channels per block

typedef unsigned long long ull;

__device__ float g_a [CS];      // exp(A*dt)
__device__ float g_cb[CS];      // C * Bd
__device__ float g_dc[CS];      // exp(A*dt*LC)
__device__ float g_v [NC*CS];   // per-chunk contribution (h0 = 0)
__device__ float g_h0[NC*CS];   // per-chunk initial state

// ---- packed f32x2 helpers (Blackwell FFMA2 path, PTX-only) ----------------
__device__ __forceinline__ ull pack2(float x, float y) {
    ull r; asm("mov.b64 %0, {%1, %2};" : "=l"(r) : "f"(x), "f"(y)); return r;
}
__device__ __forceinline__ ull fma2(ull a, ull b, ull c) {
    ull d; asm("fma.rn.f32x2 %0, %1, %2, %3;" : "=l"(d) : "l"(a), "l"(b), "l"(c)); return d;
}
__device__ __forceinline__ ull mul2(ull a, ull b) {
    ull d; asm("mul.rn.f32x2 %0, %1, %2;" : "=l"(d) : "l"(a), "l"(b)); return d;
}
__device__ __forceinline__ ull add2(ull a, ull b) {
    ull d; asm("add.rn.f32x2 %0, %1, %2;" : "=l"(d) : "l"(a), "l"(b)); return d;
}
__device__ __forceinline__ float hsum2(ull v) {
    float lo, hi; asm("mov.b64 {%0, %1}, %2;" : "=f"(lo), "=f"(hi) : "l"(v));
    return lo + hi;
}

// exp(z) for tiny |z| (<=0.016): 4th-order Taylor, rel err ~1e-12
__device__ __forceinline__ float exp_tiny(float z) {
    return 1.0f + z * (1.0f + z * (0.5f + z * (1.0f / 6.0f + z * (1.0f / 24.0f))));
}

// ---------------------------------------------------------------- pass A
// grid (NC, CH/CPB), block 256 (8 warps). Lane owns 8 states (4 pairs) of one
// channel. Decay via Taylor (no MUFU); chunk==0 blocks materialize constants.
__global__ __launch_bounds__(256, 6)
void passA_k(const float* __restrict__ x,
             const float* __restrict__ lognegA,
             const float* __restrict__ B,
             const float* __restrict__ C)
{
    __shared__ ull sx[LC][CPB];          // packed {x,x} tile, 16 KB
    const int chunk = blockIdx.x;
    const int cbase = blockIdx.y * CPB;
    const int tid   = threadIdx.x;
    const int w     = tid >> 5;
    const int lane  = tid & 31;
    const int g     = lane >> 3;      // channel within warp (0..3)
    const int q     = lane & 7;       // lane within channel team (0..7)
    const int l0    = chunk * LC;

    #pragma unroll
    for (int i = tid; i < LC * CPB / 4; i += 256) {
        int lr = i >> 3, c4 = (i & 7) << 2;
        float4 v4 = *reinterpret_cast<const float4*>(x + (l0 + lr) * CH + cbase + c4);
        sx[lr][c4 + 0] = pack2(v4.x, v4.x);
        sx[lr][c4 + 1] = pack2(v4.y, v4.y);
        sx[lr][c4 + 2] = pack2(v4.z, v4.z);
        sx[lr][c4 + 3] = pack2(v4.w, v4.w);
    }

    const int c     = cbase + w * CPW + g;
    const int sbase = c * S + q * SPL;
    const int chl   = w * CPW + g;

    // per-state decay: ad = A*dt (A = -exp(lognegA), the only MUFU);
    // a = exp(ad) via Taylor (|ad| <= 0.0156)
    float adv[SPL], av[SPL];
    #pragma unroll
    for (int t = 0; t < SPL; t++) {
        adv[t] = -__expf(lognegA[sbase + t]) * DTF;
        av [t] = exp_tiny(adv[t]);
    }
    ull a[NPK];
    #pragma unroll
    for (int t = 0; t < NPK; t++) a[t] = pack2(av[2 * t], av[2 * t + 1]);

    if (chunk == 0) {   // materialize constants for scan_k / passC_k
        #pragma unroll
        for (int t = 0; t < SPL; t++) {
            float ad = adv[t];
            // expm1(ad)/A = DTF * (1 + ad/2 + ad^2/6 + ad^3/24)
            float em = 1.0f + ad * (0.5f + ad * (1.0f / 6.0f + ad * (1.0f / 24.0f)));
            float d  = av[t];                         // a^1
            d = d * d; d = d * d; d = d * d;          // a^8
            d = d * d; d = d * d; d = d * d;          // a^64
            g_a [sbase + t] = av[t];
            g_cb[sbase + t] = C[sbase + t] * B[sbase + t] * DTF * em;
            g_dc[sbase + t] = d;
        }
    }
    __syncthreads();

    ull h[NPK] = {0ull, 0ull, 0ull, 0ull};
    #pragma unroll
    for (int l = 0; l < LC; l++) {
        ull xx = sx[l][chl];
        #pragma unroll
        for (int t = 0; t < NPK; t++) h[t] = fma2(a[t], h[t], xx);
    }

    ull* vP = reinterpret_cast<ull*>(g_v + chunk * CS + sbase);
    #pragma unroll
    for (int t = 0; t < NPK; t++) vP[t] = h[t];
}

// ---------------------------------------------------------------- chunk scan
__global__ void scan_k()
{
    int i = blockIdx.x * blockDim.x + threadIdx.x;
    if (i >= CS) return;
    const float d = g_dc[i];
    float h = 0.f;
    #pragma unroll 8
    for (int k = 0; k < NC; k++) {
        g_h0[k * CS + i] = h;
        h = fmaf(d, h, g_v[k * CS + i]);
    }
}

// ---------------------------------------------------------------- pass C
// Starts from g_h0, emits y. Packed ull tile; per step: LDS.64 + 4 FFMA2 +
// tree dot (2 mul2 + 2 fma2 + 1 add2) + hsum; 8-step buffer then 3-stage
// register-halving butterfly per 8-lane team; direct 16B-aligned stores.
__global__ __launch_bounds__(256, 5)
void passC_k(const float* __restrict__ x, float* __restrict__ y)
{
    __shared__ ull sx[LC][CPB];          // packed {x,x} tile, 16 KB
    const int chunk = blockIdx.x;
    const int cbase = blockIdx.y * CPB;
    const int tid   = threadIdx.x;
    const int w     = tid >> 5;
    const int lane  = tid & 31;
    const int g     = lane >> 3;
    const int q     = lane & 7;
    const int l0    = chunk * LC;

    #pragma unroll
    for (int i = tid; i < LC * CPB / 4; i += 256) {
        int lr = i >> 3, c4 = (i & 7) << 2;
        float4 v4 = *reinterpret_cast<const float4*>(x + (l0 + lr) * CH + cbase + c4);
        sx[lr][c4 + 0] = pack2(v4.x, v4.x);
        sx[lr][c4 + 1] = pack2(v4.y, v4.y);
        sx[lr][c4 + 2] = pack2(v4.z, v4.z);
        sx[lr][c4 + 3] = pack2(v4.w, v4.w);
    }
    __syncthreads();

    const int c     = cbase + w * CPW + g;
    const int sbase = c * S + q * SPL;
    const int chl   = w * CPW + g;

    ull a[NPK], cb[NPK], h[NPK];
    const ull* aP  = reinterpret_cast<const ull*>(g_a  + sbase);
    const ull* cbP = reinterpret_cast<const ull*>(g_cb + sbase);
    const ull* hP  = reinterpret_cast<const ull*>(g_h0 + chunk * CS + sbase);
    #pragma unroll
    for (int k = 0; k < NPK; k++) { a[k] = aP[k]; cb[k] = cbP[k]; h[k] = hP[k]; }

    #pragma unroll
    for (int r = 0; r < LC / 8; r++) {
        float p[8];
        #pragma unroll
        for (int j = 0; j < 8; j++) {
            ull xx = sx[r * 8 + j][chl];
            #pragma unroll
            for (int k = 0; k < NPK; k++) h[k] = fma2(a[k], h[k], xx);
            // tree dot: depth 3 ops instead of serial 4-op chain
            ull e0 = fma2(cb[1], h[1], mul2(cb[0], h[0]));
            ull e1 = fma2(cb[3], h[3], mul2(cb[2], h[2]));
            p[j] = hsum2(add2(e0, e1));
        }
        // 3-stage register-halving butterfly over the 8-lane team:
        // afterwards lane q holds the finished output for step r*8+q
        #pragma unroll
        for (int d = 4; d >= 1; d >>= 1) {
            #pragma unroll
            for (int m = 0; m < d; m++) {
                bool  hi   = (q & d) != 0;
                float send = hi ? p[m] : p[m + d];
                float got  = __shfl_xor_sync(0xffffffffu, send, d);
                p[m] = (hi ? p[m + d] : p[m]) + got;
            }
        }
        y[(l0 + r * 8 + q) * CH + c] = p[0];
    }
}

// ---------------------------------------------------------------- launch
extern "C" void kernel_launch(void* const* d_in, const int* in_sizes, int n_in,
                              void* d_out, int out_size)
{
    const float* x       = (const float*)d_in[0];
    const float* lognegA = (const float*)d_in[1];
    const float* B       = (const float*)d_in[2];
    const float* C       = (const float*)d_in[3];
    float*       y       = (float*)d_out;

    dim3 grid(NC, CH / CPB);
    passA_k<<<grid, 256>>>(x, lognegA, B, C);
    scan_k<<<(CS + 255) / 256, 256>>>();
    passC_k<<<grid, 256>>>(x, y);
}